// round 15
// baseline (speedup 1.0000x reference)
#include <cuda_runtime.h>
#include <cuda_bf16.h>
#include <cstdint>

#define DIM      256
#define TWO_DIM  512
#define KMAX     64
#define B_MAX    16384
#define NMT      (B_MAX / 16)
#define NKT      (DIM / 16)
#define NNT      (TWO_DIM / 8)

// ---------------- scratch (__device__ globals: allocation-guard-safe) ----------
__device__ __align__(16) uint32_t g_Afh[NMT * NKT * 32 * 4];
__device__ __align__(16) uint32_t g_Afl[NMT * NKT * 32 * 4];
__device__ __align__(16) uint32_t g_Wfh[NNT * NKT * 32 * 2];
__device__ __align__(16) uint32_t g_Wfl[NNT * NKT * 32 * 2];
__device__ __align__(128) float   g_H[B_MAX * TWO_DIM];

// ---------------- helpers ------------------------------------------------------
__device__ __forceinline__ uint32_t pack_bf16x2(float x0, float x1) {
    __nv_bfloat162 h = __floats2bfloat162_rn(x0, x1);
    return *reinterpret_cast<uint32_t*>(&h);
}
__device__ __forceinline__ void mma_bf16(float (&c)[4], const uint32_t* a,
                                         const uint32_t* b) {
    asm volatile("mma.sync.aligned.m16n8k16.row.col.f32.bf16.bf16.f32 "
                 "{%0,%1,%2,%3}, {%4,%5,%6,%7}, {%8,%9}, {%0,%1,%2,%3};"
                 : "+f"(c[0]), "+f"(c[1]), "+f"(c[2]), "+f"(c[3])
                 : "r"(a[0]), "r"(a[1]), "r"(a[2]), "r"(a[3]), "r"(b[0]), "r"(b[1]));
}
__device__ __forceinline__ uint32_t smem_u32(const void* p) {
    uint32_t a;
    asm("{ .reg .u64 t; cvta.to.shared.u64 t, %1; cvt.u32.u64 %0, t; }" : "=r"(a) : "l"(p));
    return a;
}
#define CPA16(dst, src) \
    asm volatile("cp.async.cg.shared.global [%0], [%1], 16;" :: "r"(dst), "l"(src))
#define CPA_COMMIT() asm volatile("cp.async.commit_group;" ::: "memory")
#define CPA_WAIT(n)  asm volatile("cp.async.wait_group %0;" :: "n"(n) : "memory")

// ---------------- Kernel 1: fused conv (W frags + A frags) ---------------------
__global__ __launch_bounds__(256)
void conv_all(const float* __restrict__ W,
              const int* __restrict__ nodes_v, const float* __restrict__ v2e,
              int B, int nmt)
{
    if ((int)blockIdx.x >= nmt) {
        const int blk = blockIdx.x - nmt;          // 0..127
        const int l   = threadIdx.x & 31;
        const int wid = threadIdx.x >> 5;
        const int nt  = blk >> 1;
        const int kt  = ((blk & 1) << 3) + wid;
        const int n   = nt * 8 + (l >> 2);
        uint2 hi, lo;
        #pragma unroll
        for (int r = 0; r < 2; r++) {
            const int k = kt * 16 + ((l & 3) << 1) + (r << 3);
            const float x0 = W[(size_t)k * TWO_DIM + n];
            const float x1 = W[(size_t)(k + 1) * TWO_DIM + n];
            const float h0 = __bfloat162float(__float2bfloat16_rn(x0));
            const float h1 = __bfloat162float(__float2bfloat16_rn(x1));
            (&hi.x)[r] = pack_bf16x2(x0, x1);
            (&lo.x)[r] = pack_bf16x2(x0 - h0, x1 - h1);
        }
        const size_t idx = ((size_t)nt * NKT + kt) * 32 + l;
        reinterpret_cast<uint2*>(g_Wfh)[idx] = hi;
        reinterpret_cast<uint2*>(g_Wfl)[idx] = lo;
        return;
    }
    const int mt  = blockIdx.x;
    const int l   = threadIdx.x & 31;
    const int wid = threadIdx.x >> 5;
    const int row0 = (l >> 2);
    int b0 = mt * 16 + row0;     if (b0 >= B) b0 = B - 1;
    int b1 = mt * 16 + row0 + 8; if (b1 >= B) b1 = B - 1;
    const size_t v0 = (size_t)nodes_v[b0] * DIM;
    const size_t v1 = (size_t)nodes_v[b1] * DIM;
    #pragma unroll 1
    for (int kt = wid; kt < NKT; kt += 8) {
        uint4 hi, lo;
        #pragma unroll
        for (int r = 0; r < 4; r++) {
            const int col = kt * 16 + ((l & 3) << 1) + ((r & 2) << 2);
            const size_t base = (r & 1) ? v1 : v0;
            const float x0 = v2e[base + col];
            const float x1 = v2e[base + col + 1];
            const float h0 = __bfloat162float(__float2bfloat16_rn(x0));
            const float h1 = __bfloat162float(__float2bfloat16_rn(x1));
            (&hi.x)[r] = pack_bf16x2(x0, x1);
            (&lo.x)[r] = pack_bf16x2(x0 - h0, x1 - h1);
        }
        const size_t idx = ((size_t)mt * NKT + kt) * 32 + l;
        reinterpret_cast<uint4*>(g_Afh)[idx] = hi;
        reinterpret_cast<uint4*>(g_Afl)[idx] = lo;
    }
}

// ---------------- Kernel 2: H = A @ Wt^T, frag-direct --------------------------
__global__ __launch_bounds__(256)
void gemm_mma(int B) {
    const int t   = threadIdx.x;
    const int wid = t >> 5;
    const int lid = t & 31;
    const int wm  = wid & 3;
    const int wn  = wid >> 2;
    const int m0t = blockIdx.x * 8;
    const int n0t = blockIdx.y * 16;

    float acc[2][8][4];
    #pragma unroll
    for (int mf = 0; mf < 2; mf++)
        #pragma unroll
        for (int nf = 0; nf < 8; nf++)
            #pragma unroll
            for (int q = 0; q < 4; q++) acc[mf][nf][q] = 0.f;

    const uint4* Afh4 = reinterpret_cast<const uint4*>(g_Afh);
    const uint4* Afl4 = reinterpret_cast<const uint4*>(g_Afl);
    const uint2* Wfh2 = reinterpret_cast<const uint2*>(g_Wfh);
    const uint2* Wfl2 = reinterpret_cast<const uint2*>(g_Wfl);

    #pragma unroll 2
    for (int kt = 0; kt < NKT; kt++) {
        uint4 ah[2], al[2];
        #pragma unroll
        for (int mf = 0; mf < 2; mf++) {
            const size_t ai = ((size_t)(m0t + wm * 2 + mf) * NKT + kt) * 32 + lid;
            ah[mf] = Afh4[ai];
            al[mf] = Afl4[ai];
        }
        #pragma unroll
        for (int nf = 0; nf < 8; nf++) {
            const size_t bi = ((size_t)(n0t + wn * 8 + nf) * NKT + kt) * 32 + lid;
            const uint2 bh = Wfh2[bi];
            const uint2 bl = Wfl2[bi];
            #pragma unroll
            for (int mf = 0; mf < 2; mf++) {
                mma_bf16(acc[mf][nf], &ah[mf].x, &bh.x);
                mma_bf16(acc[mf][nf], &ah[mf].x, &bl.x);
                mma_bf16(acc[mf][nf], &al[mf].x, &bh.x);
            }
        }
    }

    const int rbase = blockIdx.x * 128 + wm * 32 + (lid >> 2);
    const int cbase = blockIdx.y * 128 + wn * 64 + (lid & 3) * 2;
    #pragma unroll
    for (int mf = 0; mf < 2; mf++) {
        #pragma unroll
        for (int nf = 0; nf < 8; nf++) {
            const int row = rbase + mf * 16;
            const int col = cbase + nf * 8;
            if (row < B)
                *reinterpret_cast<float2*>(&g_H[(size_t)row * TWO_DIM + col]) =
                    make_float2(acc[mf][nf][0], acc[mf][nf][1]);
            if (row + 8 < B)
                *reinterpret_cast<float2*>(&g_H[(size_t)(row + 8) * TWO_DIM + col]) =
                    make_float2(acc[mf][nf][2], acc[mf][nf][3]);
        }
    }
}

// ---------------- Kernel 3: combine — 4-stage cp.async gather pipeline ---------
#define RPB 2
#define NTH 128
#define CHK 8
#define NSTG 4
#define ROWB (CHK * 64 * 16)               // 8 KB per row-chunk slab
#define STGB (RPB * ROWB)                  // 16 KB per stage
#define CSMEM (NSTG * STGB)                // 64 KB

__global__ __launch_bounds__(NTH)
void combine(const int* __restrict__ nodes_u,
             const int* __restrict__ nodes_v,
             const int* __restrict__ neighbors,
             const int* __restrict__ neighbor_counts,
             const float* __restrict__ u2e,
             const float* __restrict__ v2e,
             const float* __restrict__ bvec,
             float* __restrict__ out,
             int B)
{
    extern __shared__ uint4 sbuf[];        // [NSTG][RPB][CHK][64]
    __shared__ int   snb[RPB][KMAX];
    __shared__ int   scnt[RPB], su[RPB], svi[RPB], sbrow[RPB];
    __shared__ float sred[RPB][2];

    const int t    = threadIdx.x;
    const int gi   = t >> 6;               // row 0/1
    const int gt   = t & 63;
    const int c4   = gt * 4;
    const int row0 = blockIdx.x * RPB;

    {   // stage all 128 neighbor indices (one per thread)
        int r = t >> 6, k = t & 63;
        int b = row0 + r; if (b >= B) b = B - 1;
        snb[r][k] = neighbors[(size_t)b * KMAX + k];
    }
    if (t < RPB) {
        int b = row0 + t; if (b >= B) b = B - 1;
        scnt[t]  = neighbor_counts[b];
        su[t]    = nodes_u[b];
        svi[t]   = nodes_v[b];
        sbrow[t] = b;
    }
    __syncthreads();

    const int r   = gi;
    const int cnt = scnt[r];

    // hoist the non-gather loads so they fly under the gather
    const float4 b4    = *reinterpret_cast<const float4*>(&bvec[c4]);
    const float4 self4 = *reinterpret_cast<const float4*>(&u2e[(size_t)su[r]  * DIM + c4]);
    const float4 v4    = *reinterpret_cast<const float4*>(&v2e[(size_t)svi[r] * DIM + c4]);

    float partial;
    if (cnt > 0) {
        const size_t hb = (size_t)sbrow[r] * TWO_DIM;
        const float4 h1 = *reinterpret_cast<const float4*>(&g_H[hb + c4]);
        const float4 h2 = *reinterpret_cast<const float4*>(&g_H[hb + DIM + c4]);
        const int* nb = snb[r];

        const uint32_t sb_row = smem_u32(sbuf) + (uint32_t)(r * ROWB + gt * 16);
        // uint4-unit index base for reduce reads
        const uint32_t ubase = (uint32_t)(r * (ROWB / 16) + gt);

        const int nfull = cnt >> 3;
        float4 a0 = make_float4(0, 0, 0, 0), a1 = a0;

        if (nfull > 0) {
            // prologue: fill up to NSTG-1 stages
            const int np = (nfull < NSTG - 1) ? nfull : (NSTG - 1);
            #pragma unroll 1
            for (int s = 0; s < np; s++) {
                const uint32_t dst = sb_row + (uint32_t)(s * STGB);
                const int* nbc = nb + s * CHK;
                #pragma unroll
                for (int j = 0; j < CHK; j++)
                    CPA16(dst + j * 1024, &u2e[(size_t)nbc[j] * DIM + c4]);
                CPA_COMMIT();
            }
            #pragma unroll 1
            for (int c = 0; c < nfull; c++) {
                if (c + NSTG - 1 < nfull) {
                    const int cn = c + NSTG - 1;
                    const uint32_t dst = sb_row + (uint32_t)((cn & (NSTG - 1)) * STGB);
                    const int* nbc = nb + cn * CHK;
                    #pragma unroll
                    for (int j = 0; j < CHK; j++)
                        CPA16(dst + j * 1024, &u2e[(size_t)nbc[j] * DIM + c4]);
                    CPA_COMMIT();
                    CPA_WAIT(3);           // chunk c landed (3 newer in flight)
                } else {
                    const int pend = nfull - 1 - c;   // 0..2 here
                    if (pend >= 2)      CPA_WAIT(2);
                    else if (pend == 1) CPA_WAIT(1);
                    else                CPA_WAIT(0);
                }
                const uint4* src = sbuf + ubase + (uint32_t)((c & (NSTG - 1)) * (STGB / 16));
                #pragma unroll
                for (int j = 0; j < CHK; j += 2) {
                    float4 x0 = *reinterpret_cast<const float4*>(&src[j * 64]);
                    float4 x1 = *reinterpret_cast<const float4*>(&src[(j + 1) * 64]);
                    a0.x += x0.x; a0.y += x0.y; a0.z += x0.z; a0.w += x0.w;
                    a1.x += x1.x; a1.y += x1.y; a1.z += x1.z; a1.w += x1.w;
                }
            }
        }
        // tail (cnt % 8) direct
        #pragma unroll 1
        for (int k = nfull * CHK; k < cnt; k++) {
            float4 x = *reinterpret_cast<const float4*>(&u2e[(size_t)nb[k] * DIM + c4]);
            a0.x += x.x; a0.y += x.y; a0.z += x.z; a0.w += x.w;
        }
        const float inv = 1.f / (float)cnt;
        float4 nm;
        nm.x = (a0.x + a1.x) * inv;
        nm.y = (a0.y + a1.y) * inv;
        nm.z = (a0.z + a1.z) * inv;
        nm.w = (a0.w + a1.w) * inv;
        partial = self4.x * h1.x + self4.y * h1.y + self4.z * h1.z + self4.w * h1.w
                + nm.x    * h2.x + nm.y    * h2.y + nm.z    * h2.z + nm.w    * h2.w
                + b4.x    * v4.x + b4.y    * v4.y + b4.z    * v4.z + b4.w    * v4.w;
    } else {
        partial = self4.x * v4.x + self4.y * v4.y + self4.z * v4.z + self4.w * v4.w;
    }
    #pragma unroll
    for (int o = 16; o; o >>= 1)
        partial += __shfl_down_sync(0xffffffffu, partial, o);
    if ((t & 31) == 0) sred[gi][(t >> 5) & 1] = partial;
    __syncthreads();

    if (t < RPB) {
        float s = sred[t][0] + sred[t][1];
        if (row0 + t < B) out[row0 + t] = s;
    }
}

// ---------------- launch --------------------------------------------------------
extern "C" void kernel_launch(void* const* d_in, const int* in_sizes, int n_in,
                              void* d_out, int out_size)
{
    const int*   nodes_u         = (const int*)  d_in[0];
    const int*   nodes_v         = (const int*)  d_in[1];
    const int*   neighbors       = (const int*)  d_in[2];
    const int*   neighbor_counts = (const int*)  d_in[3];
    const float* u2e             = (const float*)d_in[4];
    const float* v2e             = (const float*)d_in[5];
    const float* W               = (const float*)d_in[6];
    const float* bvec            = (const float*)d_in[7];
    float*       out             = (float*)d_out;

    int B = in_sizes[0];
    if (B > B_MAX) B = B_MAX;
    const int nmt = (B + 15) / 16;

    cudaFuncSetAttribute(combine, cudaFuncAttributeMaxDynamicSharedMemorySize, CSMEM);

    conv_all<<<nmt + 128, 256>>>(W, nodes_v, v2e, B, nmt);
    dim3 ggrid((B + 127) / 128, TWO_DIM / 128);
    gemm_mma<<<ggrid, 256>>>(B);
    combine<<<(B + RPB - 1) / RPB, NTH, CSMEM>>>(nodes_u, nodes_v, neighbors,
                                                 neighbor_counts, u2e, v2e, bvec, out, B);
}

// round 16
// speedup vs baseline: 1.2652x; 1.2652x over previous
#include <cuda_runtime.h>
#include <cuda_bf16.h>
#include <cstdint>

#define DIM      256
#define TWO_DIM  512
#define KMAX     64
#define B_MAX    16384
#define NMT      (B_MAX / 16)
#define NKT      (DIM / 16)
#define NNT      (TWO_DIM / 8)

// ---------------- scratch (__device__ globals: allocation-guard-safe) ----------
__device__ __align__(16) uint32_t g_Afh[NMT * NKT * 32 * 4];
__device__ __align__(16) uint32_t g_Afl[NMT * NKT * 32 * 4];
__device__ __align__(16) uint32_t g_Wfh[NNT * NKT * 32 * 2];
__device__ __align__(16) uint32_t g_Wfl[NNT * NKT * 32 * 2];
__device__ __align__(128) float   g_H[B_MAX * TWO_DIM];

// ---------------- helpers ------------------------------------------------------
__device__ __forceinline__ uint32_t pack_bf16x2(float x0, float x1) {
    __nv_bfloat162 h = __floats2bfloat162_rn(x0, x1);
    return *reinterpret_cast<uint32_t*>(&h);
}
__device__ __forceinline__ void mma_bf16(float (&c)[4], const uint32_t* a,
                                         const uint32_t* b) {
    asm volatile("mma.sync.aligned.m16n8k16.row.col.f32.bf16.bf16.f32 "
                 "{%0,%1,%2,%3}, {%4,%5,%6,%7}, {%8,%9}, {%0,%1,%2,%3};"
                 : "+f"(c[0]), "+f"(c[1]), "+f"(c[2]), "+f"(c[3])
                 : "r"(a[0]), "r"(a[1]), "r"(a[2]), "r"(a[3]), "r"(b[0]), "r"(b[1]));
}
__device__ __forceinline__ uint32_t smem_u32(const void* p) {
    uint32_t a;
    asm("{ .reg .u64 t; cvta.to.shared.u64 t, %1; cvt.u32.u64 %0, t; }" : "=r"(a) : "l"(p));
    return a;
}
#define CPA16(dst, src) \
    asm volatile("cp.async.cg.shared.global [%0], [%1], 16;" :: "r"(dst), "l"(src))
#define CPA_COMMIT() asm volatile("cp.async.commit_group;" ::: "memory")
#define CPA_WAIT(n)  asm volatile("cp.async.wait_group %0;" :: "n"(n) : "memory")

// ---------------- Kernel 1: fused conv (W frags + A frags) ---------------------
__global__ __launch_bounds__(256)
void conv_all(const float* __restrict__ W,
              const int* __restrict__ nodes_v, const float* __restrict__ v2e,
              int B, int nmt)
{
    if ((int)blockIdx.x >= nmt) {
        const int blk = blockIdx.x - nmt;          // 0..127
        const int l   = threadIdx.x & 31;
        const int wid = threadIdx.x >> 5;
        const int nt  = blk >> 1;
        const int kt  = ((blk & 1) << 3) + wid;
        const int n   = nt * 8 + (l >> 2);
        uint2 hi, lo;
        #pragma unroll
        for (int r = 0; r < 2; r++) {
            const int k = kt * 16 + ((l & 3) << 1) + (r << 3);
            const float x0 = W[(size_t)k * TWO_DIM + n];
            const float x1 = W[(size_t)(k + 1) * TWO_DIM + n];
            const float h0 = __bfloat162float(__float2bfloat16_rn(x0));
            const float h1 = __bfloat162float(__float2bfloat16_rn(x1));
            (&hi.x)[r] = pack_bf16x2(x0, x1);
            (&lo.x)[r] = pack_bf16x2(x0 - h0, x1 - h1);
        }
        const size_t idx = ((size_t)nt * NKT + kt) * 32 + l;
        reinterpret_cast<uint2*>(g_Wfh)[idx] = hi;
        reinterpret_cast<uint2*>(g_Wfl)[idx] = lo;
        return;
    }
    const int mt  = blockIdx.x;
    const int l   = threadIdx.x & 31;
    const int wid = threadIdx.x >> 5;
    const int row0 = (l >> 2);
    int b0 = mt * 16 + row0;     if (b0 >= B) b0 = B - 1;
    int b1 = mt * 16 + row0 + 8; if (b1 >= B) b1 = B - 1;
    const size_t v0 = (size_t)nodes_v[b0] * DIM;
    const size_t v1 = (size_t)nodes_v[b1] * DIM;
    #pragma unroll 1
    for (int kt = wid; kt < NKT; kt += 8) {
        uint4 hi, lo;
        #pragma unroll
        for (int r = 0; r < 4; r++) {
            const int col = kt * 16 + ((l & 3) << 1) + ((r & 2) << 2);
            const size_t base = (r & 1) ? v1 : v0;
            const float x0 = v2e[base + col];
            const float x1 = v2e[base + col + 1];
            const float h0 = __bfloat162float(__float2bfloat16_rn(x0));
            const float h1 = __bfloat162float(__float2bfloat16_rn(x1));
            (&hi.x)[r] = pack_bf16x2(x0, x1);
            (&lo.x)[r] = pack_bf16x2(x0 - h0, x1 - h1);
        }
        const size_t idx = ((size_t)mt * NKT + kt) * 32 + l;
        reinterpret_cast<uint4*>(g_Afh)[idx] = hi;
        reinterpret_cast<uint4*>(g_Afl)[idx] = lo;
    }
}

// ---------------- Kernel 2: H = A @ Wt^T, smem-staged fragments ----------------
// CTA 128m x 128n, 8 warps. Per kt-slice the CTA stages A (8 mtiles, hi+lo)
// and W (16 ntiles, hi+lo) fragments in smem once; warps share via LDS.
// L2 traffic: 131 MB total (3x less than frag-direct).
__global__ __launch_bounds__(256)
void gemm_mma(int B) {
    // stage buffers: A[2][2(hl)][8 mt][32] uint4 ; W[2][2(hl)][16 nt][16] uint4
    __shared__ uint4 sA[2][2][8][32];      // 2 * 8 KB
    __shared__ uint4 sW[2][2][16][16];     // 2 * 8 KB

    const int t   = threadIdx.x;
    const int wid = t >> 5;
    const int lid = t & 31;
    const int wm  = wid & 3;
    const int wn  = wid >> 2;
    const int m0t = blockIdx.x * 8;
    const int n0t = blockIdx.y * 16;

    float acc[2][8][4];
    #pragma unroll
    for (int mf = 0; mf < 2; mf++)
        #pragma unroll
        for (int nf = 0; nf < 8; nf++)
            #pragma unroll
            for (int q = 0; q < 4; q++) acc[mf][nf][q] = 0.f;

    const uint32_t sAu = smem_u32(&sA[0][0][0][0]);
    const uint32_t sWu = smem_u32(&sW[0][0][0][0]);

    // stage kt-slice into buffer s: 512 A uint4 + 512 W uint4, 4 cp.async/thread
    auto stage = [&](int kt, int s) {
        // A: idx in [0,512): hl = idx>>8, mt = (idx>>5)&7, lane = idx&31
        #pragma unroll
        for (int rep = 0; rep < 2; rep++) {
            const int idx  = rep * 256 + t;
            const int hl   = idx >> 8;
            const int mt   = (idx >> 5) & 7;
            const int lane = idx & 31;
            const uint32_t* src = hl ? g_Afl : g_Afh;
            const size_t gi = (((size_t)(m0t + mt) * NKT + kt) * 32 + lane) * 4;
            CPA16(sAu + (uint32_t)(((s * 2 + hl) * 8 + mt) * 32 + lane) * 16, &src[gi]);
        }
        // W: idx in [0,512): hl = idx>>8, nt = (idx>>4)&15, j = idx&15
        #pragma unroll
        for (int rep = 0; rep < 2; rep++) {
            const int idx = rep * 256 + t;
            const int hl  = idx >> 8;
            const int nt  = (idx >> 4) & 15;
            const int j   = idx & 15;
            const uint32_t* src = hl ? g_Wfl : g_Wfh;
            const size_t gi = (((size_t)(n0t + nt) * NKT + kt) * 16 + j) * 4;  // uint4 units
            CPA16(sWu + (uint32_t)(((s * 2 + hl) * 16 + nt) * 16 + j) * 16, &src[gi]);
        }
        CPA_COMMIT();
    };

    stage(0, 0);

    #pragma unroll 1
    for (int kt = 0; kt < NKT; kt++) {
        const int buf = kt & 1;
        if (kt + 1 < NKT) { stage(kt + 1, buf ^ 1); CPA_WAIT(1); }
        else              { CPA_WAIT(0); }
        __syncthreads();

        uint4 ah[2], al[2];
        #pragma unroll
        for (int mf = 0; mf < 2; mf++) {
            const int mt = wm * 2 + mf;
            ah[mf] = sA[buf][0][mt][lid];
            al[mf] = sA[buf][1][mt][lid];
        }
        #pragma unroll
        for (int nf = 0; nf < 8; nf++) {
            const int nt = wn * 8 + nf;
            const uint2 bh = *reinterpret_cast<const uint2*>(
                reinterpret_cast<const uint32_t*>(&sW[buf][0][nt][0]) + lid * 2);
            const uint2 bl = *reinterpret_cast<const uint2*>(
                reinterpret_cast<const uint32_t*>(&sW[buf][1][nt][0]) + lid * 2);
            #pragma unroll
            for (int mf = 0; mf < 2; mf++) {
                mma_bf16(acc[mf][nf], &ah[mf].x, &bh.x);   // hi*hi
                mma_bf16(acc[mf][nf], &ah[mf].x, &bl.x);   // hi*lo
                mma_bf16(acc[mf][nf], &al[mf].x, &bh.x);   // lo*hi
            }
        }
        __syncthreads();   // protect buf before kt+2's stage overwrites it
    }

    const int rbase = blockIdx.x * 128 + wm * 32 + (lid >> 2);
    const int cbase = blockIdx.y * 128 + wn * 64 + (lid & 3) * 2;
    #pragma unroll
    for (int mf = 0; mf < 2; mf++) {
        #pragma unroll
        for (int nf = 0; nf < 8; nf++) {
            const int row = rbase + mf * 16;
            const int col = cbase + nf * 8;
            if (row < B)
                *reinterpret_cast<float2*>(&g_H[(size_t)row * TWO_DIM + col]) =
                    make_float2(acc[mf][nf][0], acc[mf][nf][1]);
            if (row + 8 < B)
                *reinterpret_cast<float2*>(&g_H[(size_t)(row + 8) * TWO_DIM + col]) =
                    make_float2(acc[mf][nf][2], acc[mf][nf][3]);
        }
    }
}

// ---------------- Kernel 3: combine — round-13 proven version ------------------
#define RPB 4
#define NTH 256
#define CHK 8
#define CSMEM (2 * RPB * CHK * 64 * 16)    // 64 KB

__global__ __launch_bounds__(NTH)
void combine(const int* __restrict__ nodes_u,
             const int* __restrict__ nodes_v,
             const int* __restrict__ neighbors,
             const int* __restrict__ neighbor_counts,
             const float* __restrict__ u2e,
             const float* __restrict__ v2e,
             const float* __restrict__ bvec,
             float* __restrict__ out,
             int B)
{
    extern __shared__ uint4 sbuf[];        // [2][RPB][CHK][64]
    __shared__ int   snb[RPB][KMAX];
    __shared__ int   scnt[RPB], su[RPB], svi[RPB], sbrow[RPB];
    __shared__ float sred[RPB][2];

    const int t    = threadIdx.x;
    const int gi   = t >> 6;
    const int gt   = t & 63;
    const int c4   = gt * 4;
    const int row0 = blockIdx.x * RPB;

    if (t < RPB * KMAX) {
        int r = t >> 6, k = t & 63;
        int b = row0 + r; if (b >= B) b = B - 1;
        snb[r][k] = neighbors[(size_t)b * KMAX + k];
    }
    if (t < RPB) {
        int b = row0 + t; if (b >= B) b = B - 1;
        scnt[t]  = neighbor_counts[b];
        su[t]    = nodes_u[b];
        svi[t]   = nodes_v[b];
        sbrow[t] = b;
    }
    __syncthreads();

    const float4 b4 = *reinterpret_cast<const float4*>(&bvec[c4]);

    const int r   = gi;
    const int cnt = scnt[r];
    const float4 self4 = *reinterpret_cast<const float4*>(&u2e[(size_t)su[r]  * DIM + c4]);
    const float4 v4    = *reinterpret_cast<const float4*>(&v2e[(size_t)svi[r] * DIM + c4]);
    float partial;
    if (cnt > 0) {
        const size_t hb = (size_t)sbrow[r] * TWO_DIM;
        const float4 h1 = *reinterpret_cast<const float4*>(&g_H[hb + c4]);
        const float4 h2 = *reinterpret_cast<const float4*>(&g_H[hb + DIM + c4]);
        const int* nb = snb[r];
        const uint32_t sb0 = smem_u32(sbuf) + (uint32_t)(((r * CHK) * 64 + gt) * 16);
        const uint32_t bufstride = (uint32_t)(RPB * CHK * 64 * 16);
        const int nfull = cnt >> 3;

        float4 a0 = make_float4(0, 0, 0, 0), a1 = a0;

        if (nfull > 0) {
            #pragma unroll
            for (int j = 0; j < CHK; j++)
                CPA16(sb0 + j * 64 * 16, &u2e[(size_t)nb[j] * DIM + c4]);
            CPA_COMMIT();
            #pragma unroll 1
            for (int c = 1; c < nfull; c++) {
                const uint32_t dsty = sb0 + (c & 1) * bufstride;
                const int* nbc = nb + c * CHK;
                #pragma unroll
                for (int j = 0; j < CHK; j++)
                    CPA16(dsty + j * 64 * 16, &u2e[(size_t)nbc[j] * DIM + c4]);
                CPA_COMMIT();
                CPA_WAIT(1);
                const uint4* src = reinterpret_cast<const uint4*>(
                    sbuf + ((size_t)((c - 1) & 1) * RPB * CHK * 64) + (size_t)r * CHK * 64 + gt);
                #pragma unroll
                for (int j = 0; j < CHK; j += 2) {
                    float4 x0 = *reinterpret_cast<const float4*>(&src[j * 64]);
                    float4 x1 = *reinterpret_cast<const float4*>(&src[(j + 1) * 64]);
                    a0.x += x0.x; a0.y += x0.y; a0.z += x0.z; a0.w += x0.w;
                    a1.x += x1.x; a1.y += x1.y; a1.z += x1.z; a1.w += x1.w;
                }
            }
            CPA_WAIT(0);
            const uint4* src = reinterpret_cast<const uint4*>(
                sbuf + ((size_t)((nfull - 1) & 1) * RPB * CHK * 64) + (size_t)r * CHK * 64 + gt);
            #pragma unroll
            for (int j = 0; j < CHK; j += 2) {
                float4 x0 = *reinterpret_cast<const float4*>(&src[j * 64]);
                float4 x1 = *reinterpret_cast<const float4*>(&src[(j + 1) * 64]);
                a0.x += x0.x; a0.y += x0.y; a0.z += x0.z; a0.w += x0.w;
                a1.x += x1.x; a1.y += x1.y; a1.z += x1.z; a1.w += x1.w;
            }
        }
        #pragma unroll 1
        for (int k = nfull * CHK; k < cnt; k++) {
            float4 x = *reinterpret_cast<const float4*>(&u2e[(size_t)nb[k] * DIM + c4]);
            a0.x += x.x; a0.y += x.y; a0.z += x.z; a0.w += x.w;
        }
        const float inv = 1.f / (float)cnt;
        float4 nm;
        nm.x = (a0.x + a1.x) * inv;
        nm.y = (a0.y + a1.y) * inv;
        nm.z = (a0.z + a1.z) * inv;
        nm.w = (a0.w + a1.w) * inv;
        partial = self4.x * h1.x + self4.y * h1.y + self4.z * h1.z + self4.w * h1.w
                + nm.x    * h2.x + nm.y    * h2.y + nm.z    * h2.z + nm.w    * h2.w
                + b4.x    * v4.x + b4.y    * v4.y + b4.z    * v4.z + b4.w    * v4.w;
    } else {
        partial = self4.x * v4.x + self4.y * v4.y + self4.z * v4.z + self4.w * v4.w;
    }
    #pragma unroll
    for (int o = 16; o; o >>= 1)
        partial += __shfl_down_sync(0xffffffffu, partial, o);
    if ((t & 31) == 0) sred[r][(t >> 5) & 1] = partial;
    __syncthreads();

    if (t < RPB) {
        float s = sred[t][0] + sred[t][1];
        if (row0 + t < B) out[row0 + t] = s;
    }
}

// ---------------- launch --------------------------------------------------------
extern "C" void kernel_launch(void* const* d_in, const int* in_sizes, int n_in,
                              void* d_out, int out_size)
{
    const int*   nodes_u         = (const int*)  d_in[0];
    const int*   nodes_v         = (const int*)  d_in[1];
    const int*   neighbors       = (const int*)  d_in[2];
    const int*   neighbor_counts = (const int*)  d_in[3];
    const float* u2e             = (const float*)d_in[4];
    const float* v2e             = (const float*)d_in[5];
    const float* W               = (const float*)d_in[6];
    const float* bvec            = (const float*)d_in[7];
    float*       out             = (float*)d_out;

    int B = in_sizes[0];
    if (B > B_MAX) B = B_MAX;
    const int nmt = (B + 15) / 16;

    cudaFuncSetAttribute(combine, cudaFuncAttributeMaxDynamicSharedMemorySize, CSMEM);

    conv_all<<<nmt + 128, 256>>>(W, nodes_v, v2e, B, nmt);
    dim3 ggrid((B + 127) / 128, TWO_DIM / 128);
    gemm_mma<<<ggrid, 256>>>(B);
    combine<<<(B + RPB - 1) / RPB, NTH, CSMEM>>>(nodes_u, nodes_v, neighbors,
                                                 neighbor_counts, u2e, v2e, bvec, out, B);
}